// round 9
// baseline (speedup 1.0000x reference)
#include <cuda_runtime.h>
#include <math.h>

#define NN 10000
#define EE 160000
#define FF 32
#define NCH 9

// ---------------- device scratch (static, no allocations) ----------------
__device__ float g_x[NN * NCH * FF];     // node features
__device__ float g_y[NN * NCH * FF];     // message accumulator
__device__ float g_geo[EE * 25];         // per edge: sph[9], rad[16]

struct CGc { float v[729]; };

// ---------------- host: analytic Gaunt coefficients -----------------------
static double dfact_h(int n) { double v = 1.0; for (int k = n; k >= 2; k -= 2) v *= (double)k; return v; }

static void compute_cg(CGc* cg) {
    const double c0 = 0.28209479177387814, c1 = 0.4886025119029199,
                 c2a = 1.0925484305920792, c2b = 0.31539156525252005,
                 c2c = 0.5462742152960396;
    double tc[9][2]; int te[9][2][3]; int nt[9];
    for (int i = 0; i < 9; i++) { nt[i] = 1; tc[i][1] = 0.0; te[i][1][0] = te[i][1][1] = te[i][1][2] = 0; }
    tc[0][0] = c0;      te[0][0][0]=0; te[0][0][1]=0; te[0][0][2]=0;
    tc[1][0] = c1;      te[1][0][0]=0; te[1][0][1]=1; te[1][0][2]=0;
    tc[2][0] = c1;      te[2][0][0]=0; te[2][0][1]=0; te[2][0][2]=1;
    tc[3][0] = c1;      te[3][0][0]=1; te[3][0][1]=0; te[3][0][2]=0;
    tc[4][0] = c2a;     te[4][0][0]=1; te[4][0][1]=1; te[4][0][2]=0;
    tc[5][0] = c2a;     te[5][0][0]=0; te[5][0][1]=1; te[5][0][2]=1;
    tc[6][0] = 3.0*c2b; te[6][0][0]=0; te[6][0][1]=0; te[6][0][2]=2;
    tc[6][1] = -c2b;    te[6][1][0]=0; te[6][1][1]=0; te[6][1][2]=0; nt[6] = 2;
    tc[7][0] = c2a;     te[7][0][0]=1; te[7][0][1]=0; te[7][0][2]=1;
    tc[8][0] = c2c;     te[8][0][0]=2; te[8][0][1]=0; te[8][0][2]=0;
    tc[8][1] = -c2c;    te[8][1][0]=0; te[8][1][1]=2; te[8][1][2]=0; nt[8] = 2;

    const double fourpi = 12.566370614359172464;
    for (int a = 0; a < 9; a++)
      for (int b = 0; b < 9; b++)
        for (int c = 0; c < 9; c++) {
            double g = 0.0;
            for (int i = 0; i < nt[a]; i++)
              for (int j = 0; j < nt[b]; j++)
                for (int k = 0; k < nt[c]; k++) {
                    int p = te[a][i][0] + te[b][j][0] + te[c][k][0];
                    int q = te[a][i][1] + te[b][j][1] + te[c][k][1];
                    int r = te[a][i][2] + te[b][j][2] + te[c][k][2];
                    if ((p | q | r) & 1) continue;
                    double I = fourpi * dfact_h(p - 1) * dfact_h(q - 1) * dfact_h(r - 1)
                               / dfact_h(p + q + r + 1);
                    g += tc[a][i] * tc[b][j] * tc[c][k] * I;
                }
            if (fabs(g) < 1e-6) g = 0.0;
            cg->v[(a * 9 + b) * 9 + c] = (float)g;
        }
}

// ---------------- kernels -------------------------------------------------

__global__ void k_init(const int* __restrict__ z, const float* __restrict__ embed) {
    int idx = blockIdx.x * blockDim.x + threadIdx.x;
    if (idx >= NN * NCH * FF) return;
    g_y[idx] = 0.0f;
    int f = idx & 31;
    int c = (idx >> 5) % 9;
    int n = idx / (NCH * FF);
    g_x[idx] = (c == 0) ? embed[z[n] * FF + f] : 0.0f;
}

__global__ void k_geom(const float* __restrict__ pos, const int* __restrict__ dst,
                       const int* __restrict__ src) {
    int e = blockIdx.x * blockDim.x + threadIdx.x;
    if (e >= EE) return;
    int s = src[e], d = dst[e];
    float dx = pos[s * 3 + 0] - pos[d * 3 + 0];
    float dy = pos[s * 3 + 1] - pos[d * 3 + 1];
    float dz = pos[s * 3 + 2] - pos[d * 3 + 2];
    float r = sqrtf(dx * dx + dy * dy + dz * dz + 1e-12f);
    float inv = 1.0f / r;
    float x = dx * inv, y = dy * inv, z = dz * inv;
    const float c0 = 0.28209479177387814f, c1 = 0.4886025119029199f,
                c2a = 1.0925484305920792f, c2b = 0.31539156525252005f,
                c2c = 0.5462742152960396f;
    float* g = &g_geo[(size_t)e * 25];
    g[0] = c0;
    g[1] = c1 * y;  g[2] = c1 * z;  g[3] = c1 * x;
    g[4] = c2a * x * y; g[5] = c2a * y * z;
    g[6] = c2b * (3.0f * z * z - 1.0f);
    g[7] = c2a * x * z; g[8] = c2c * (x * x - y * y);

    float u1 = 1.0f / (1.0f + r);
    float om = 1.0f - u1;
    float A[16], B[16];
    A[0] = 1.0f;
    #pragma unroll
    for (int k = 1; k < 16; k++) A[k] = A[k - 1] * u1;
    B[15] = 1.0f;
    #pragma unroll
    for (int k = 14; k >= 0; k--) B[k] = B[k + 1] * om;
    float t = r * 0.25f;
    float fc = 0.0f;
    if (t < 1.0f) {
        float den = 1.0f - t * t;
        fc = expf(-t * t / den);
    }
    const float binom[16] = {1.f,15.f,105.f,455.f,1365.f,3003.f,5005.f,6435.f,
                             6435.f,5005.f,3003.f,1365.f,455.f,105.f,15.f,1.f};
    #pragma unroll
    for (int k = 0; k < 16; k++) g[9 + k] = binom[k] * A[k] * B[k] * fc;
}

__global__ void __launch_bounds__(256, 2)
k_edge(const int* __restrict__ dst, const int* __restrict__ src,
       const float* __restrict__ Wb_i, CGc cg) {
    const int lane = threadIdx.x & 31;
    const int warp = (blockIdx.x * blockDim.x + threadIdx.x) >> 5;
    const int nwarp = (gridDim.x * blockDim.x) >> 5;

    float w0[16], w1[16], w2[16];
    #pragma unroll
    for (int n = 0; n < 16; n++) {
        w0[n] = Wb_i[(0 * 16 + n) * 32 + lane];
        w1[n] = Wb_i[(1 * 16 + n) * 32 + lane];
        w2[n] = Wb_i[(2 * 16 + n) * 32 + lane];
    }

    for (int e = warp; e < EE; e += nwarp) {
        int s = src[e], d = dst[e];
        float gv = g_geo[(size_t)e * 25 + (lane < 25 ? lane : 0)];

        float R0 = 0.f, R1 = 0.f, R2 = 0.f;
        #pragma unroll
        for (int n = 0; n < 16; n++) {
            float rn = __shfl_sync(0xffffffffu, gv, 9 + n);
            R0 = fmaf(rn, w0[n], R0);
            R1 = fmaf(rn, w1[n], R1);
            R2 = fmaf(rn, w2[n], R2);
        }
        float bfv[9];
        #pragma unroll
        for (int b = 0; b < 9; b++) {
            float sb = __shfl_sync(0xffffffffu, gv, b);
            bfv[b] = sb * (b == 0 ? R0 : (b < 4 ? R1 : R2));
        }
        float xa[9];
        const float* xp = &g_x[(size_t)s * 288 + lane];
        #pragma unroll
        for (int a = 0; a < 9; a++) xa[a] = xp[a * 32];

        float msg[9];
        #pragma unroll
        for (int c = 0; c < 9; c++) msg[c] = 0.f;

#define GV(A,B,C) cg.v[(A)*81 + (B)*9 + (C)]
#define TPA(A,B,C) msg[C] = fmaf(GV(A,B,C), xa[A] * bfv[B], msg[C]);
#define TPS(A,B,C) msg[C] = fmaf(GV(A,B,C), fmaf(xa[A], bfv[B], xa[B] * bfv[A]), msg[C]);
        TPA(0,0,0) TPA(1,1,0) TPA(2,2,0) TPA(3,3,0) TPA(4,4,0)
        TPA(5,5,0) TPA(6,6,0) TPA(7,7,0) TPA(8,8,0)
        TPS(0,6,0) TPS(0,8,0) TPS(6,8,0)
        TPA(0,0,6) TPA(1,1,6) TPA(2,2,6) TPA(3,3,6) TPA(4,4,6)
        TPA(5,5,6) TPA(6,6,6) TPA(7,7,6) TPA(8,8,6)
        TPS(0,6,6) TPS(0,8,6) TPS(6,8,6)
        TPA(0,0,8) TPA(1,1,8) TPA(2,2,8) TPA(3,3,8) TPA(4,4,8)
        TPA(5,5,8) TPA(6,6,8) TPA(7,7,8) TPA(8,8,8)
        TPS(0,6,8) TPS(0,8,8) TPS(6,8,8)
        TPS(0,1,1) TPS(6,1,1) TPS(8,1,1) TPS(3,4,1) TPS(2,5,1)
        TPS(0,2,2) TPS(6,2,2) TPS(8,2,2) TPS(3,7,2) TPS(1,5,2)
        TPS(0,3,3) TPS(6,3,3) TPS(8,3,3) TPS(1,4,3) TPS(2,7,3)
        TPS(0,4,4) TPS(6,4,4) TPS(8,4,4) TPS(1,3,4) TPS(5,7,4)
        TPS(0,5,5) TPS(6,5,5) TPS(8,5,5) TPS(1,2,5) TPS(4,7,5)
        TPS(0,7,7) TPS(6,7,7) TPS(8,7,7) TPS(2,3,7) TPS(4,5,7)
#undef GV
#undef TPA
#undef TPS

        float* yp = &g_y[(size_t)d * 288 + lane];
        #pragma unroll
        for (int c = 0; c < 9; c++) atomicAdd(&yp[c * 32], msg[c]);
    }
}

// node kernel v3: warp-autonomous. The equivariant dense layers are
// channel-diagonal, so warp c does the full update for channel c with NO
// block barriers. Weights live in registers; activations broadcast through
// a warp-private smem row. Two nodes per iteration for ILP.
//   y = x + agg; h = silu(W1 y + b1); x += W2 h + b2.  Re-zeroes g_y.
__global__ void __launch_bounds__(288, 2)
k_node(const float* __restrict__ W1, const float* __restrict__ b1,
       const float* __restrict__ W2, const float* __restrict__ b2) {
    __shared__ float sbuf[9][2][32];
    const int t = threadIdx.x;
    const int c = t >> 5, lane = t & 31;
    const int DEGc[9] = {0, 1, 1, 1, 2, 2, 2, 2, 2};
    const int d = DEGc[c];

    float w1c[32], w2c[32];
    #pragma unroll
    for (int f = 0; f < 32; f++) {
        w1c[f] = W1[(d * 32 + f) * 32 + lane];
        w2c[f] = W2[(d * 32 + f) * 32 + lane];
    }
    const float b1g = (c == 0) ? b1[lane] : 0.0f;
    const float b2g = (c == 0) ? b2[lane] : 0.0f;

    const float4* pa = (const float4*)sbuf[c][0];
    const float4* pb = (const float4*)sbuf[c][1];

    for (int n = blockIdx.x * 2; n < NN; n += gridDim.x * 2) {   // NN even
        const int ia = n * 288 + c * 32 + lane;
        const int ib = ia + 288;
        float xr_a = g_x[ia], xr_b = g_x[ib];
        float ya = xr_a + g_y[ia];
        float yb = xr_b + g_y[ib];
        g_y[ia] = 0.0f;
        g_y[ib] = 0.0f;
        sbuf[c][0][lane] = ya;
        sbuf[c][1][lane] = yb;
        __syncwarp();

        float a0 = b1g, a1 = 0.f, a2 = 0.f, a3 = 0.f;
        float e0 = b1g, e1 = 0.f, e2 = 0.f, e3 = 0.f;
        #pragma unroll
        for (int j = 0; j < 8; j++) {
            float4 qa = pa[j];
            float4 qb = pb[j];
            a0 = fmaf(qa.x, w1c[4 * j + 0], a0);
            a1 = fmaf(qa.y, w1c[4 * j + 1], a1);
            a2 = fmaf(qa.z, w1c[4 * j + 2], a2);
            a3 = fmaf(qa.w, w1c[4 * j + 3], a3);
            e0 = fmaf(qb.x, w1c[4 * j + 0], e0);
            e1 = fmaf(qb.y, w1c[4 * j + 1], e1);
            e2 = fmaf(qb.z, w1c[4 * j + 2], e2);
            e3 = fmaf(qb.w, w1c[4 * j + 3], e3);
        }
        float sa = (a0 + a1) + (a2 + a3);
        float sb = (e0 + e1) + (e2 + e3);
        float ha = sa / (1.0f + __expf(-sa));
        float hb = sb / (1.0f + __expf(-sb));
        __syncwarp();
        sbuf[c][0][lane] = ha;
        sbuf[c][1][lane] = hb;
        __syncwarp();

        a0 = b2g; a1 = 0.f; a2 = 0.f; a3 = 0.f;
        e0 = b2g; e1 = 0.f; e2 = 0.f; e3 = 0.f;
        #pragma unroll
        for (int j = 0; j < 8; j++) {
            float4 qa = pa[j];
            float4 qb = pb[j];
            a0 = fmaf(qa.x, w2c[4 * j + 0], a0);
            a1 = fmaf(qa.y, w2c[4 * j + 1], a1);
            a2 = fmaf(qa.z, w2c[4 * j + 2], a2);
            a3 = fmaf(qa.w, w2c[4 * j + 3], a3);
            e0 = fmaf(qb.x, w2c[4 * j + 0], e0);
            e1 = fmaf(qb.y, w2c[4 * j + 1], e1);
            e2 = fmaf(qb.z, w2c[4 * j + 2], e2);
            e3 = fmaf(qb.w, w2c[4 * j + 3], e3);
        }
        g_x[ia] = xr_a + (a0 + a1) + (a2 + a3);
        g_x[ib] = xr_b + (e0 + e1) + (e2 + e3);
        __syncwarp();   // reads of sbuf done before next-iter overwrite
    }
}

// output head: mono (N,4) then dip (N,3,4)
__global__ void __launch_bounds__(256)
k_out(const int* __restrict__ z, const float* __restrict__ pos,
      const float* __restrict__ Wt00, const float* __restrict__ Wt11,
      const float* __restrict__ Wmono, const float* __restrict__ ebias,
      float* __restrict__ out) {
    int lane = threadIdx.x & 31;
    int n = (blockIdx.x * blockDim.x + threadIdx.x) >> 5;
    if (n >= NN) return;

    float x0 = g_x[n * 288 + lane];
    float tj[4];
    #pragma unroll
    for (int j = 0; j < 4; j++) {
        float p = x0 * Wt00[lane * 4 + j];
        #pragma unroll
        for (int o = 16; o > 0; o >>= 1) p += __shfl_xor_sync(0xffffffffu, p, o);
        tj[j] = p;
    }
    if (lane < 4) {
        float m = 0.0f;
        #pragma unroll
        for (int k = 0; k < 4; k++) m = fmaf(tj[k], Wmono[k * 4 + lane], m);
        m += ebias[z[n]];
        out[n * 4 + lane] = m;
    }
    #pragma unroll
    for (int c = 0; c < 3; c++) {
        float xc = g_x[n * 288 + (1 + c) * 32 + lane];
        #pragma unroll
        for (int j = 0; j < 4; j++) {
            float p = xc * Wt11[lane * 4 + j];
            #pragma unroll
            for (int o = 16; o > 0; o >>= 1) p += __shfl_xor_sync(0xffffffffu, p, o);
            if (lane == 0) {
                float sv = p / (1.0f + expf(-p));
                sv = fminf(fmaxf(sv, -0.3f), 0.3f);
                out[NN * 4 + (n * 3 + c) * 4 + j] = sv + pos[n * 3 + c];
            }
        }
    }
}

// ---------------- launch --------------------------------------------------
extern "C" void kernel_launch(void* const* d_in, const int* in_sizes, int n_in,
                              void* d_out, int out_size) {
    const int*   z     = (const int*)d_in[0];
    const float* pos   = (const float*)d_in[1];
    const int*   dst   = (const int*)d_in[2];
    const int*   src   = (const int*)d_in[3];
    const float* embed = (const float*)d_in[4];
    const float* Wb    = (const float*)d_in[5];
    const float* W1    = (const float*)d_in[6];
    const float* b1    = (const float*)d_in[7];
    const float* W2    = (const float*)d_in[8];
    const float* b2    = (const float*)d_in[9];
    const float* Wt00  = (const float*)d_in[10];
    const float* Wt11  = (const float*)d_in[11];
    const float* Wmono = (const float*)d_in[12];
    const float* ebias = (const float*)d_in[13];
    float* out = (float*)d_out;

    CGc cg;
    compute_cg(&cg);

    k_init<<<(NN * NCH * FF + 255) / 256, 256>>>(z, embed);
    k_geom<<<(EE + 255) / 256, 256>>>(pos, dst, src);
    for (int i = 0; i < 3; i++) {
        k_edge<<<2048, 256>>>(dst, src, Wb + i * 3 * 16 * 32, cg);
        k_node<<<1250, 288>>>(W1 + i * 3 * 32 * 32, b1 + i * 32,
                              W2 + i * 3 * 32 * 32, b2 + i * 32);
    }
    k_out<<<(NN * 32 + 255) / 256, 256>>>(z, pos, Wt00, Wt11, Wmono, ebias, out);
}

// round 12
// speedup vs baseline: 1.1036x; 1.1036x over previous
#include <cuda_runtime.h>
#include <math.h>

#define NN 10000
#define EE 160000
#define FF 32
#define NCH 9

// ---------------- device scratch (static, no allocations) ----------------
__device__ float g_x[NN * NCH * FF];     // node features
__device__ float g_y[NN * NCH * FF];     // message accumulator
__device__ float g_geo[EE * 25];         // per edge: sph[9], rad[16]

// ---------------- compile-time Gaunt coefficients -------------------------
// Host-side compile-time evaluation only: the table is a constexpr VARIABLE
// (legal to reference from device code; literal indexing folds to immediates).
constexpr double dfc(int n) { double v = 1.0; for (int k = n; k >= 2; k -= 2) v *= (double)k; return v; }
constexpr double sphint(int p, int q, int r) {
    return ((p | q | r) & 1) ? 0.0
         : 12.566370614359172464 * dfc(p - 1) * dfc(q - 1) * dfc(r - 1) / dfc(p + q + r + 1);
}
struct CGTable { float v[9][9][9]; };
constexpr CGTable make_cg() {
    const double TCV[9][2] = {
        {0.28209479177387814, 0.0}, {0.4886025119029199, 0.0}, {0.4886025119029199, 0.0},
        {0.4886025119029199, 0.0}, {1.0925484305920792, 0.0}, {1.0925484305920792, 0.0},
        {3.0 * 0.31539156525252005, -0.31539156525252005}, {1.0925484305920792, 0.0},
        {0.5462742152960396, -0.5462742152960396}};
    const int NTV[9] = {1, 1, 1, 1, 1, 1, 2, 1, 2};
    const int TEV[9][2][3] = {
        {{0,0,0},{0,0,0}}, {{0,1,0},{0,0,0}}, {{0,0,1},{0,0,0}}, {{1,0,0},{0,0,0}},
        {{1,1,0},{0,0,0}}, {{0,1,1},{0,0,0}}, {{0,0,2},{0,0,0}}, {{1,0,1},{0,0,0}},
        {{2,0,0},{0,2,0}}};
    CGTable t{};
    for (int a = 0; a < 9; a++)
      for (int b = 0; b < 9; b++)
        for (int c = 0; c < 9; c++) {
            double g = 0.0;
            for (int i = 0; i < NTV[a]; i++)
              for (int j = 0; j < NTV[b]; j++)
                for (int k = 0; k < NTV[c]; k++)
                    g += TCV[a][i] * TCV[b][j] * TCV[c][k] *
                         sphint(TEV[a][i][0] + TEV[b][j][0] + TEV[c][k][0],
                                TEV[a][i][1] + TEV[b][j][1] + TEV[c][k][1],
                                TEV[a][i][2] + TEV[b][j][2] + TEV[c][k][2]);
            if (g < 1e-6 && g > -1e-6) g = 0.0;
            t.v[a][b][c] = (float)g;
        }
    return t;
}
constexpr CGTable CG_TAB = make_cg();

// ---------------- kernels -------------------------------------------------

__global__ void k_init(const int* __restrict__ z, const float* __restrict__ embed) {
    int idx = blockIdx.x * blockDim.x + threadIdx.x;
    if (idx >= NN * NCH * FF) return;
    g_y[idx] = 0.0f;
    int f = idx & 31;
    int c = (idx >> 5) % 9;
    int n = idx / (NCH * FF);
    g_x[idx] = (c == 0) ? embed[z[n] * FF + f] : 0.0f;
}

__global__ void k_geom(const float* __restrict__ pos, const int* __restrict__ dst,
                       const int* __restrict__ src) {
    int e = blockIdx.x * blockDim.x + threadIdx.x;
    if (e >= EE) return;
    int s = src[e], d = dst[e];
    float dx = pos[s * 3 + 0] - pos[d * 3 + 0];
    float dy = pos[s * 3 + 1] - pos[d * 3 + 1];
    float dz = pos[s * 3 + 2] - pos[d * 3 + 2];
    float r = sqrtf(dx * dx + dy * dy + dz * dz + 1e-12f);
    float inv = 1.0f / r;
    float x = dx * inv, y = dy * inv, z = dz * inv;
    const float c0 = 0.28209479177387814f, c1 = 0.4886025119029199f,
                c2a = 1.0925484305920792f, c2b = 0.31539156525252005f,
                c2c = 0.5462742152960396f;
    float* g = &g_geo[(size_t)e * 25];
    g[0] = c0;
    g[1] = c1 * y;  g[2] = c1 * z;  g[3] = c1 * x;
    g[4] = c2a * x * y; g[5] = c2a * y * z;
    g[6] = c2b * (3.0f * z * z - 1.0f);
    g[7] = c2a * x * z; g[8] = c2c * (x * x - y * y);

    float u1 = 1.0f / (1.0f + r);
    float om = 1.0f - u1;
    float A[16], B[16];
    A[0] = 1.0f;
    #pragma unroll
    for (int k = 1; k < 16; k++) A[k] = A[k - 1] * u1;
    B[15] = 1.0f;
    #pragma unroll
    for (int k = 14; k >= 0; k--) B[k] = B[k + 1] * om;
    float t = r * 0.25f;
    float fc = 0.0f;
    if (t < 1.0f) {
        float den = 1.0f - t * t;
        fc = expf(-t * t / den);
    }
    const float binom[16] = {1.f,15.f,105.f,455.f,1365.f,3003.f,5005.f,6435.f,
                             6435.f,5005.f,3003.f,1365.f,455.f,105.f,15.f,1.f};
    #pragma unroll
    for (int k = 0; k < 16; k++) g[9 + k] = binom[k] * A[k] * B[k] * fc;
}

// edge kernel: CG as compile-time immediates (FFMA-imm, rt=1) + shared products.
__global__ void __launch_bounds__(256, 2)
k_edge(const int* __restrict__ dst, const int* __restrict__ src,
       const float* __restrict__ Wb_i) {
    const int lane = threadIdx.x & 31;
    const int warp = (blockIdx.x * blockDim.x + threadIdx.x) >> 5;
    const int nwarp = (gridDim.x * blockDim.x) >> 5;

    float w0[16], w1[16], w2[16];
    #pragma unroll
    for (int n = 0; n < 16; n++) {
        w0[n] = Wb_i[(0 * 16 + n) * 32 + lane];
        w1[n] = Wb_i[(1 * 16 + n) * 32 + lane];
        w2[n] = Wb_i[(2 * 16 + n) * 32 + lane];
    }

    for (int e = warp; e < EE; e += nwarp) {
        int s = src[e], d = dst[e];
        float gv = g_geo[(size_t)e * 25 + (lane < 25 ? lane : 0)];

        float R0 = 0.f, R1 = 0.f, R2 = 0.f;
        #pragma unroll
        for (int n = 0; n < 16; n++) {
            float rn = __shfl_sync(0xffffffffu, gv, 9 + n);
            R0 = fmaf(rn, w0[n], R0);
            R1 = fmaf(rn, w1[n], R1);
            R2 = fmaf(rn, w2[n], R2);
        }
        float bfv[9];
        #pragma unroll
        for (int b = 0; b < 9; b++) {
            float sb = __shfl_sync(0xffffffffu, gv, b);
            bfv[b] = sb * (b == 0 ? R0 : (b < 4 ? R1 : R2));
        }
        float xa[9];
        const float* xp = &g_x[(size_t)s * 288 + lane];
        #pragma unroll
        for (int a = 0; a < 9; a++) xa[a] = xp[a * 32];

        float msg[9];
        #pragma unroll
        for (int c = 0; c < 9; c++) msg[c] = 0.f;

        // diagonal products p_a = xa[a]*bfv[a], feed c in {0,6,8}
        float p[9];
        #pragma unroll
        for (int a = 0; a < 9; a++) p[a] = xa[a] * bfv[a];
#define ACCP(A,C) { constexpr float G_ = CG_TAB.v[A][A][C]; if (G_ != 0.0f) msg[C] = fmaf(p[A], G_, msg[C]); }
#define CROSS(A,B) float s##A##B = fmaf(xa[A], bfv[B], xa[B] * bfv[A]);
#define ACCS(A,B,C) { constexpr float G_ = CG_TAB.v[A][B][C]; if (G_ != 0.0f) msg[C] = fmaf(s##A##B, G_, msg[C]); }
        // diagonal terms, literal indices
        ACCP(0,0) ACCP(0,6) ACCP(0,8)
        ACCP(1,0) ACCP(1,6) ACCP(1,8)
        ACCP(2,0) ACCP(2,6) ACCP(2,8)
        ACCP(3,0) ACCP(3,6) ACCP(3,8)
        ACCP(4,0) ACCP(4,6) ACCP(4,8)
        ACCP(5,0) ACCP(5,6) ACCP(5,8)
        ACCP(6,0) ACCP(6,6) ACCP(6,8)
        ACCP(7,0) ACCP(7,6) ACCP(7,8)
        ACCP(8,0) ACCP(8,6) ACCP(8,8)

        // cross products, each computed once, reused across output channels
        CROSS(0,6) CROSS(0,8) CROSS(6,8)
        ACCS(0,6,0) ACCS(0,6,6) ACCS(0,6,8)
        ACCS(0,8,0) ACCS(0,8,6) ACCS(0,8,8)
        ACCS(6,8,0) ACCS(6,8,6) ACCS(6,8,8)

        CROSS(0,1) CROSS(6,1) CROSS(8,1) CROSS(3,4) CROSS(2,5)
        ACCS(0,1,1) ACCS(6,1,1) ACCS(8,1,1) ACCS(3,4,1) ACCS(2,5,1)

        CROSS(0,2) CROSS(6,2) CROSS(8,2) CROSS(3,7) CROSS(1,5)
        ACCS(0,2,2) ACCS(6,2,2) ACCS(8,2,2) ACCS(3,7,2) ACCS(1,5,2)

        CROSS(0,3) CROSS(6,3) CROSS(8,3) CROSS(1,4) CROSS(2,7)
        ACCS(0,3,3) ACCS(6,3,3) ACCS(8,3,3) ACCS(1,4,3) ACCS(2,7,3)

        CROSS(0,4) CROSS(6,4) CROSS(8,4) CROSS(1,3) CROSS(5,7)
        ACCS(0,4,4) ACCS(6,4,4) ACCS(8,4,4) ACCS(1,3,4) ACCS(5,7,4)

        CROSS(0,5) CROSS(6,5) CROSS(8,5) CROSS(1,2) CROSS(4,7)
        ACCS(0,5,5) ACCS(6,5,5) ACCS(8,5,5) ACCS(1,2,5) ACCS(4,7,5)

        CROSS(0,7) CROSS(6,7) CROSS(8,7) CROSS(2,3) CROSS(4,5)
        ACCS(0,7,7) ACCS(6,7,7) ACCS(8,7,7) ACCS(2,3,7) ACCS(4,5,7)
#undef ACCP
#undef CROSS
#undef ACCS

        float* yp = &g_y[(size_t)d * 288 + lane];
        #pragma unroll
        for (int c = 0; c < 9; c++) atomicAdd(&yp[c * 32], msg[c]);
    }
}

// node kernel (R2 version, best measured): warp per node, lane = feature,
// shfl-broadcast matmul with weights staged in smem.
__global__ void __launch_bounds__(256)
k_node(const float* __restrict__ W1, const float* __restrict__ b1,
       const float* __restrict__ W2, const float* __restrict__ b2) {
    __shared__ float sW1[3 * 32 * 32], sW2[3 * 32 * 32], sb1[32], sb2[32];
    int t = threadIdx.x;
    for (int i = t; i < 3072; i += 256) { sW1[i] = W1[i]; sW2[i] = W2[i]; }
    if (t < 32) { sb1[t] = b1[t]; sb2[t] = b2[t]; }
    __syncthreads();

    int lane = t & 31;
    int n = (blockIdx.x * 256 + t) >> 5;
    if (n >= NN) return;

    const int DEGc[9] = {0, 1, 1, 1, 2, 2, 2, 2, 2};
    float yv[9], h[9];
    #pragma unroll
    for (int c = 0; c < 9; c++) {
        int idx = n * 288 + c * 32 + lane;
        yv[c] = g_x[idx] + g_y[idx];
        g_y[idx] = 0.0f;
    }
    #pragma unroll
    for (int c = 0; c < 9; c++) {
        int d = DEGc[c];
        float acc = (c == 0) ? sb1[lane] : 0.0f;
        #pragma unroll
        for (int f = 0; f < 32; f++) {
            float v = __shfl_sync(0xffffffffu, yv[c], f);
            acc = fmaf(v, sW1[(d * 32 + f) * 32 + lane], acc);
        }
        h[c] = acc / (1.0f + __expf(-acc));   // silu
    }
    #pragma unroll
    for (int c = 0; c < 9; c++) {
        int d = DEGc[c];
        float acc = (c == 0) ? sb2[lane] : 0.0f;
        #pragma unroll
        for (int f = 0; f < 32; f++) {
            float v = __shfl_sync(0xffffffffu, h[c], f);
            acc = fmaf(v, sW2[(d * 32 + f) * 32 + lane], acc);
        }
        g_x[n * 288 + c * 32 + lane] += acc;
    }
}

// output head: mono (N,4) then dip (N,3,4)
__global__ void __launch_bounds__(256)
k_out(const int* __restrict__ z, const float* __restrict__ pos,
      const float* __restrict__ Wt00, const float* __restrict__ Wt11,
      const float* __restrict__ Wmono, const float* __restrict__ ebias,
      float* __restrict__ out) {
    int lane = threadIdx.x & 31;
    int n = (blockIdx.x * blockDim.x + threadIdx.x) >> 5;
    if (n >= NN) return;

    float x0 = g_x[n * 288 + lane];
    float tj[4];
    #pragma unroll
    for (int j = 0; j < 4; j++) {
        float p = x0 * Wt00[lane * 4 + j];
        #pragma unroll
        for (int o = 16; o > 0; o >>= 1) p += __shfl_xor_sync(0xffffffffu, p, o);
        tj[j] = p;
    }
    if (lane < 4) {
        float m = 0.0f;
        #pragma unroll
        for (int k = 0; k < 4; k++) m = fmaf(tj[k], Wmono[k * 4 + lane], m);
        m += ebias[z[n]];
        out[n * 4 + lane] = m;
    }
    #pragma unroll
    for (int c = 0; c < 3; c++) {
        float xc = g_x[n * 288 + (1 + c) * 32 + lane];
        #pragma unroll
        for (int j = 0; j < 4; j++) {
            float p = xc * Wt11[lane * 4 + j];
            #pragma unroll
            for (int o = 16; o > 0; o >>= 1) p += __shfl_xor_sync(0xffffffffu, p, o);
            if (lane == 0) {
                float sv = p / (1.0f + expf(-p));
                sv = fminf(fmaxf(sv, -0.3f), 0.3f);
                out[NN * 4 + (n * 3 + c) * 4 + j] = sv + pos[n * 3 + c];
            }
        }
    }
}

// ---------------- launch --------------------------------------------------
extern "C" void kernel_launch(void* const* d_in, const int* in_sizes, int n_in,
                              void* d_out, int out_size) {
    const int*   z     = (const int*)d_in[0];
    const float* pos   = (const float*)d_in[1];
    const int*   dst   = (const int*)d_in[2];
    const int*   src   = (const int*)d_in[3];
    const float* embed = (const float*)d_in[4];
    const float* Wb    = (const float*)d_in[5];
    const float* W1    = (const float*)d_in[6];
    const float* b1    = (const float*)d_in[7];
    const float* W2    = (const float*)d_in[8];
    const float* b2    = (const float*)d_in[9];
    const float* Wt00  = (const float*)d_in[10];
    const float* Wt11  = (const float*)d_in[11];
    const float* Wmono = (const float*)d_in[12];
    const float* ebias = (const float*)d_in[13];
    float* out = (float*)d_out;

    k_init<<<(NN * NCH * FF + 255) / 256, 256>>>(z, embed);
    k_geom<<<(EE + 255) / 256, 256>>>(pos, dst, src);
    for (int i = 0; i < 3; i++) {
        k_edge<<<2048, 256>>>(dst, src, Wb + i * 3 * 16 * 32);
        k_node<<<(NN * 32 + 255) / 256, 256>>>(W1 + i * 3 * 32 * 32, b1 + i * 32,
                                               W2 + i * 3 * 32 * 32, b2 + i * 32);
    }
    k_out<<<(NN * 32 + 255) / 256, 256>>>(z, pos, Wt00, Wt11, Wmono, ebias, out);
}

// round 13
// speedup vs baseline: 1.1685x; 1.0588x over previous
#include <cuda_runtime.h>
#include <math.h>

#define NN 10000
#define EE 160000
#define FF 32
#define NCH 9
#define NPAD 12                 // padded channel dim (16B-aligned lane chunks)
#define NODE_F4 (FF * NPAD / 4) // 96 float4 per node

// ---------------- device scratch (static, no allocations) ----------------
// layout: [node][feature][channel(padded to 12)]
__device__ float4 g_x4[NN * NODE_F4];
__device__ float4 g_y4[NN * NODE_F4];
__device__ float  g_geo[EE * 25];   // per edge: sph[9], rad[16]

// ---------------- compile-time Gaunt coefficients -------------------------
constexpr double dfc(int n) { double v = 1.0; for (int k = n; k >= 2; k -= 2) v *= (double)k; return v; }
constexpr double sphint(int p, int q, int r) {
    return ((p | q | r) & 1) ? 0.0
         : 12.566370614359172464 * dfc(p - 1) * dfc(q - 1) * dfc(r - 1) / dfc(p + q + r + 1);
}
struct CGTable { float v[9][9][9]; };
constexpr CGTable make_cg() {
    const double TCV[9][2] = {
        {0.28209479177387814, 0.0}, {0.4886025119029199, 0.0}, {0.4886025119029199, 0.0},
        {0.4886025119029199, 0.0}, {1.0925484305920792, 0.0}, {1.0925484305920792, 0.0},
        {3.0 * 0.31539156525252005, -0.31539156525252005}, {1.0925484305920792, 0.0},
        {0.5462742152960396, -0.5462742152960396}};
    const int NTV[9] = {1, 1, 1, 1, 1, 1, 2, 1, 2};
    const int TEV[9][2][3] = {
        {{0,0,0},{0,0,0}}, {{0,1,0},{0,0,0}}, {{0,0,1},{0,0,0}}, {{1,0,0},{0,0,0}},
        {{1,1,0},{0,0,0}}, {{0,1,1},{0,0,0}}, {{0,0,2},{0,0,0}}, {{1,0,1},{0,0,0}},
        {{2,0,0},{0,2,0}}};
    CGTable t{};
    for (int a = 0; a < 9; a++)
      for (int b = 0; b < 9; b++)
        for (int c = 0; c < 9; c++) {
            double g = 0.0;
            for (int i = 0; i < NTV[a]; i++)
              for (int j = 0; j < NTV[b]; j++)
                for (int k = 0; k < NTV[c]; k++)
                    g += TCV[a][i] * TCV[b][j] * TCV[c][k] *
                         sphint(TEV[a][i][0] + TEV[b][j][0] + TEV[c][k][0],
                                TEV[a][i][1] + TEV[b][j][1] + TEV[c][k][1],
                                TEV[a][i][2] + TEV[b][j][2] + TEV[c][k][2]);
            if (g < 1e-6 && g > -1e-6) g = 0.0;
            t.v[a][b][c] = (float)g;
        }
    return t;
}
constexpr CGTable CG_TAB = make_cg();

// ---------------- kernels -------------------------------------------------

__global__ void k_init(const int* __restrict__ z, const float* __restrict__ embed) {
    int idx = blockIdx.x * blockDim.x + threadIdx.x;      // float4 index
    if (idx >= NN * NODE_F4) return;
    g_y4[idx] = make_float4(0.f, 0.f, 0.f, 0.f);
    int r = idx % NODE_F4;          // 0..95
    int n = idx / NODE_F4;
    int f = r / 3, part = r % 3;    // part 0 holds channels 0-3
    float v0 = (part == 0) ? embed[z[n] * FF + f] : 0.0f;
    g_x4[idx] = make_float4(v0, 0.f, 0.f, 0.f);
}

__global__ void k_geom(const float* __restrict__ pos, const int* __restrict__ dst,
                       const int* __restrict__ src) {
    int e = blockIdx.x * blockDim.x + threadIdx.x;
    if (e >= EE) return;
    int s = src[e], d = dst[e];
    float dx = pos[s * 3 + 0] - pos[d * 3 + 0];
    float dy = pos[s * 3 + 1] - pos[d * 3 + 1];
    float dz = pos[s * 3 + 2] - pos[d * 3 + 2];
    float r = sqrtf(dx * dx + dy * dy + dz * dz + 1e-12f);
    float inv = 1.0f / r;
    float x = dx * inv, y = dy * inv, z = dz * inv;
    const float c0 = 0.28209479177387814f, c1 = 0.4886025119029199f,
                c2a = 1.0925484305920792f, c2b = 0.31539156525252005f,
                c2c = 0.5462742152960396f;
    float* g = &g_geo[(size_t)e * 25];
    g[0] = c0;
    g[1] = c1 * y;  g[2] = c1 * z;  g[3] = c1 * x;
    g[4] = c2a * x * y; g[5] = c2a * y * z;
    g[6] = c2b * (3.0f * z * z - 1.0f);
    g[7] = c2a * x * z; g[8] = c2c * (x * x - y * y);

    float u1 = 1.0f / (1.0f + r);
    float om = 1.0f - u1;
    float A[16], B[16];
    A[0] = 1.0f;
    #pragma unroll
    for (int k = 1; k < 16; k++) A[k] = A[k - 1] * u1;
    B[15] = 1.0f;
    #pragma unroll
    for (int k = 14; k >= 0; k--) B[k] = B[k + 1] * om;
    float t = r * 0.25f;
    float fc = 0.0f;
    if (t < 1.0f) {
        float den = 1.0f - t * t;
        fc = expf(-t * t / den);
    }
    const float binom[16] = {1.f,15.f,105.f,455.f,1365.f,3003.f,5005.f,6435.f,
                             6435.f,5005.f,3003.f,1365.f,455.f,105.f,15.f,1.f};
    #pragma unroll
    for (int k = 0; k < 16; k++) g[9 + k] = binom[k] * A[k] * B[k] * fc;
}

// edge kernel: vectorized gather/scatter + prefetch pipeline + CG immediates.
__global__ void __launch_bounds__(256, 2)
k_edge(const int* __restrict__ dst, const int* __restrict__ src,
       const float* __restrict__ Wb_i) {
    const int lane = threadIdx.x & 31;
    const int warp = (blockIdx.x * blockDim.x + threadIdx.x) >> 5;
    const int nwarp = (gridDim.x * blockDim.x) >> 5;
    const int lsel = (lane < 25 ? lane : 0);

    float w0[16], w1[16], w2[16];
    #pragma unroll
    for (int n = 0; n < 16; n++) {
        w0[n] = Wb_i[(0 * 16 + n) * 32 + lane];
        w1[n] = Wb_i[(1 * 16 + n) * 32 + lane];
        w2[n] = Wb_i[(2 * 16 + n) * 32 + lane];
    }

    float* gx = (float*)g_x4;
    float* gy = (float*)g_y4;

    int e = warp;
    int s = 0, d = 0; float gv = 0.0f;
    if (e < EE) {
        s = src[e]; d = dst[e];
        gv = g_geo[(size_t)e * 25 + lsel];
    }
    for (; e < EE; e += nwarp) {
        // gather x[src] early (latency overlaps the shfl chain below)
        const float4* xp4 = (const float4*)(gx + (size_t)s * (FF * NPAD) + lane * NPAD);
        float4 xv0 = xp4[0];
        float4 xv1 = xp4[1];
        float  xa8 = ((const float*)xp4)[8];

        // prefetch next edge
        int en = e + nwarp;
        int s2 = 0, d2 = 0; float gv2 = 0.0f;
        if (en < EE) {
            s2 = src[en]; d2 = dst[en];
            gv2 = g_geo[(size_t)en * 25 + lsel];
        }

        float R0 = 0.f, R1 = 0.f, R2 = 0.f;
        #pragma unroll
        for (int n = 0; n < 16; n++) {
            float rn = __shfl_sync(0xffffffffu, gv, 9 + n);
            R0 = fmaf(rn, w0[n], R0);
            R1 = fmaf(rn, w1[n], R1);
            R2 = fmaf(rn, w2[n], R2);
        }
        float bfv[9];
        #pragma unroll
        for (int b = 0; b < 9; b++) {
            float sb = __shfl_sync(0xffffffffu, gv, b);
            bfv[b] = sb * (b == 0 ? R0 : (b < 4 ? R1 : R2));
        }
        float xa[9] = {xv0.x, xv0.y, xv0.z, xv0.w, xv1.x, xv1.y, xv1.z, xv1.w, xa8};

        float msg[9];
        #pragma unroll
        for (int c = 0; c < 9; c++) msg[c] = 0.f;

        float p[9];
        #pragma unroll
        for (int a = 0; a < 9; a++) p[a] = xa[a] * bfv[a];
#define ACCP(A,C) { constexpr float G_ = CG_TAB.v[A][A][C]; if (G_ != 0.0f) msg[C] = fmaf(p[A], G_, msg[C]); }
#define CROSS(A,B) float s##A##B = fmaf(xa[A], bfv[B], xa[B] * bfv[A]);
#define ACCS(A,B,C) { constexpr float G_ = CG_TAB.v[A][B][C]; if (G_ != 0.0f) msg[C] = fmaf(s##A##B, G_, msg[C]); }
        ACCP(0,0) ACCP(0,6) ACCP(0,8)
        ACCP(1,0) ACCP(1,6) ACCP(1,8)
        ACCP(2,0) ACCP(2,6) ACCP(2,8)
        ACCP(3,0) ACCP(3,6) ACCP(3,8)
        ACCP(4,0) ACCP(4,6) ACCP(4,8)
        ACCP(5,0) ACCP(5,6) ACCP(5,8)
        ACCP(6,0) ACCP(6,6) ACCP(6,8)
        ACCP(7,0) ACCP(7,6) ACCP(7,8)
        ACCP(8,0) ACCP(8,6) ACCP(8,8)

        CROSS(0,6) CROSS(0,8) CROSS(6,8)
        ACCS(0,6,0) ACCS(0,6,6) ACCS(0,6,8)
        ACCS(0,8,0) ACCS(0,8,6) ACCS(0,8,8)
        ACCS(6,8,0) ACCS(6,8,6) ACCS(6,8,8)

        CROSS(0,1) CROSS(6,1) CROSS(8,1) CROSS(3,4) CROSS(2,5)
        ACCS(0,1,1) ACCS(6,1,1) ACCS(8,1,1) ACCS(3,4,1) ACCS(2,5,1)

        CROSS(0,2) CROSS(6,2) CROSS(8,2) CROSS(3,7) CROSS(1,5)
        ACCS(0,2,2) ACCS(6,2,2) ACCS(8,2,2) ACCS(3,7,2) ACCS(1,5,2)

        CROSS(0,3) CROSS(6,3) CROSS(8,3) CROSS(1,4) CROSS(2,7)
        ACCS(0,3,3) ACCS(6,3,3) ACCS(8,3,3) ACCS(1,4,3) ACCS(2,7,3)

        CROSS(0,4) CROSS(6,4) CROSS(8,4) CROSS(1,3) CROSS(5,7)
        ACCS(0,4,4) ACCS(6,4,4) ACCS(8,4,4) ACCS(1,3,4) ACCS(5,7,4)

        CROSS(0,5) CROSS(6,5) CROSS(8,5) CROSS(1,2) CROSS(4,7)
        ACCS(0,5,5) ACCS(6,5,5) ACCS(8,5,5) ACCS(1,2,5) ACCS(4,7,5)

        CROSS(0,7) CROSS(6,7) CROSS(8,7) CROSS(2,3) CROSS(4,5)
        ACCS(0,7,7) ACCS(6,7,7) ACCS(8,7,7) ACCS(2,3,7) ACCS(4,5,7)
#undef ACCP
#undef CROSS
#undef ACCS

        float4* yp4 = (float4*)(gy + (size_t)d * (FF * NPAD) + lane * NPAD);
        atomicAdd(yp4 + 0, make_float4(msg[0], msg[1], msg[2], msg[3]));
        atomicAdd(yp4 + 1, make_float4(msg[4], msg[5], msg[6], msg[7]));
        atomicAdd((float*)(yp4 + 2), msg[8]);

        s = s2; d = d2; gv = gv2;
    }
}

// node kernel: warp per node, lane = feature, shfl-broadcast matmul
// (best-measured form), float4 loads/stores in the padded layout.
__global__ void __launch_bounds__(256)
k_node(const float* __restrict__ W1, const float* __restrict__ b1,
       const float* __restrict__ W2, const float* __restrict__ b2) {
    __shared__ float sW1[3 * 32 * 32], sW2[3 * 32 * 32], sb1[32], sb2[32];
    int t = threadIdx.x;
    for (int i = t; i < 3072; i += 256) { sW1[i] = W1[i]; sW2[i] = W2[i]; }
    if (t < 32) { sb1[t] = b1[t]; sb2[t] = b2[t]; }
    __syncthreads();

    int lane = t & 31;
    int n = (blockIdx.x * 256 + t) >> 5;
    if (n >= NN) return;

    const int base4 = n * NODE_F4 + lane * 3;
    float4 xA = g_x4[base4 + 0], xB = g_x4[base4 + 1], xC = g_x4[base4 + 2];
    float4 yA = g_y4[base4 + 0], yB = g_y4[base4 + 1], yC = g_y4[base4 + 2];
    float4 z4 = make_float4(0.f, 0.f, 0.f, 0.f);
    g_y4[base4 + 0] = z4; g_y4[base4 + 1] = z4; g_y4[base4 + 2] = z4;

    const int DEGc[9] = {0, 1, 1, 1, 2, 2, 2, 2, 2};
    float yv[9], h[9], o[9];
    yv[0] = xA.x + yA.x; yv[1] = xA.y + yA.y; yv[2] = xA.z + yA.z; yv[3] = xA.w + yA.w;
    yv[4] = xB.x + yB.x; yv[5] = xB.y + yB.y; yv[6] = xB.z + yB.z; yv[7] = xB.w + yB.w;
    yv[8] = xC.x + yC.x;

    #pragma unroll
    for (int c = 0; c < 9; c++) {
        int d = DEGc[c];
        float acc = (c == 0) ? sb1[lane] : 0.0f;
        #pragma unroll
        for (int f = 0; f < 32; f++) {
            float v = __shfl_sync(0xffffffffu, yv[c], f);
            acc = fmaf(v, sW1[(d * 32 + f) * 32 + lane], acc);
        }
        h[c] = acc / (1.0f + __expf(-acc));   // silu
    }
    #pragma unroll
    for (int c = 0; c < 9; c++) {
        int d = DEGc[c];
        float acc = (c == 0) ? sb2[lane] : 0.0f;
        #pragma unroll
        for (int f = 0; f < 32; f++) {
            float v = __shfl_sync(0xffffffffu, h[c], f);
            acc = fmaf(v, sW2[(d * 32 + f) * 32 + lane], acc);
        }
        o[c] = acc;
    }
    g_x4[base4 + 0] = make_float4(xA.x + o[0], xA.y + o[1], xA.z + o[2], xA.w + o[3]);
    g_x4[base4 + 1] = make_float4(xB.x + o[4], xB.y + o[5], xB.z + o[6], xB.w + o[7]);
    g_x4[base4 + 2] = make_float4(xC.x + o[8], 0.f, 0.f, 0.f);
}

// output head: mono (N,4) then dip (N,3,4)
__global__ void __launch_bounds__(256)
k_out(const int* __restrict__ z, const float* __restrict__ pos,
      const float* __restrict__ Wt00, const float* __restrict__ Wt11,
      const float* __restrict__ Wmono, const float* __restrict__ ebias,
      float* __restrict__ out) {
    int lane = threadIdx.x & 31;
    int n = (blockIdx.x * blockDim.x + threadIdx.x) >> 5;
    if (n >= NN) return;
    const float* gx = (const float*)g_x4;
    const size_t nb = (size_t)n * (FF * NPAD) + lane * NPAD;

    float x0 = gx[nb + 0];
    float tj[4];
    #pragma unroll
    for (int j = 0; j < 4; j++) {
        float p = x0 * Wt00[lane * 4 + j];
        #pragma unroll
        for (int o = 16; o > 0; o >>= 1) p += __shfl_xor_sync(0xffffffffu, p, o);
        tj[j] = p;
    }
    if (lane < 4) {
        float m = 0.0f;
        #pragma unroll
        for (int k = 0; k < 4; k++) m = fmaf(tj[k], Wmono[k * 4 + lane], m);
        m += ebias[z[n]];
        out[n * 4 + lane] = m;
    }
    #pragma unroll
    for (int c = 0; c < 3; c++) {
        float xc = gx[nb + 1 + c];
        #pragma unroll
        for (int j = 0; j < 4; j++) {
            float p = xc * Wt11[lane * 4 + j];
            #pragma unroll
            for (int o = 16; o > 0; o >>= 1) p += __shfl_xor_sync(0xffffffffu, p, o);
            if (lane == 0) {
                float sv = p / (1.0f + expf(-p));
                sv = fminf(fmaxf(sv, -0.3f), 0.3f);
                out[NN * 4 + (n * 3 + c) * 4 + j] = sv + pos[n * 3 + c];
            }
        }
    }
}

// ---------------- launch --------------------------------------------------
extern "C" void kernel_launch(void* const* d_in, const int* in_sizes, int n_in,
                              void* d_out, int out_size) {
    const int*   z     = (const int*)d_in[0];
    const float* pos   = (const float*)d_in[1];
    const int*   dst   = (const int*)d_in[2];
    const int*   src   = (const int*)d_in[3];
    const float* embed = (const float*)d_in[4];
    const float* Wb    = (const float*)d_in[5];
    const float* W1    = (const float*)d_in[6];
    const float* b1    = (const float*)d_in[7];
    const float* W2    = (const float*)d_in[8];
    const float* b2    = (const float*)d_in[9];
    const float* Wt00  = (const float*)d_in[10];
    const float* Wt11  = (const float*)d_in[11];
    const float* Wmono = (const float*)d_in[12];
    const float* ebias = (const float*)d_in[13];
    float* out = (float*)d_out;

    k_init<<<(NN * NODE_F4 + 255) / 256, 256>>>(z, embed);
    k_geom<<<(EE + 255) / 256, 256>>>(pos, dst, src);
    for (int i = 0; i < 3; i++) {
        k_edge<<<2048, 256>>>(dst, src, Wb + i * 3 * 16 * 32);
        k_node<<<(NN * 32 + 255) / 256, 256>>>(W1 + i * 3 * 32 * 32, b1 + i * 32,
                                               W2 + i * 3 * 32 * 32, b2 + i * 32);
    }
    k_out<<<(NN * 32 + 255) / 256, 256>>>(z, pos, Wt00, Wt11, Wmono, ebias, out);
}

// round 14
// speedup vs baseline: 1.3278x; 1.1363x over previous
#include <cuda_runtime.h>
#include <math.h>

#define NN 10000
#define EE 160000
#define FF 32
#define NCH 9
#define NPAD 12                 // padded channel dim (16B-aligned lane chunks)
#define NODE_F4 (FF * NPAD / 4) // 96 float4 per node

// ---------------- device scratch (static, no allocations) ----------------
__device__ float4 g_x4[NN * NODE_F4];    // [node][feature][ch(12)]
__device__ float4 g_y4[NN * NODE_F4];    // message sum (fully overwritten per iter)
__device__ float  g_geo[EE * 25];        // per edge: sph[9], rad[16]
__device__ int    g_cnt[NN];             // histogram / scatter cursor
__device__ int    g_off[NN + 1];         // CSR offsets
__device__ int    g_csr_src[EE];         // src node per CSR slot
__device__ int    g_csr_eid[EE];         // original edge id per CSR slot

// ---------------- compile-time Gaunt coefficients -------------------------
constexpr double dfc(int n) { double v = 1.0; for (int k = n; k >= 2; k -= 2) v *= (double)k; return v; }
constexpr double sphint(int p, int q, int r) {
    return ((p | q | r) & 1) ? 0.0
         : 12.566370614359172464 * dfc(p - 1) * dfc(q - 1) * dfc(r - 1) / dfc(p + q + r + 1);
}
struct CGTable { float v[9][9][9]; };
constexpr CGTable make_cg() {
    const double TCV[9][2] = {
        {0.28209479177387814, 0.0}, {0.4886025119029199, 0.0}, {0.4886025119029199, 0.0},
        {0.4886025119029199, 0.0}, {1.0925484305920792, 0.0}, {1.0925484305920792, 0.0},
        {3.0 * 0.31539156525252005, -0.31539156525252005}, {1.0925484305920792, 0.0},
        {0.5462742152960396, -0.5462742152960396}};
    const int NTV[9] = {1, 1, 1, 1, 1, 1, 2, 1, 2};
    const int TEV[9][2][3] = {
        {{0,0,0},{0,0,0}}, {{0,1,0},{0,0,0}}, {{0,0,1},{0,0,0}}, {{1,0,0},{0,0,0}},
        {{1,1,0},{0,0,0}}, {{0,1,1},{0,0,0}}, {{0,0,2},{0,0,0}}, {{1,0,1},{0,0,0}},
        {{2,0,0},{0,2,0}}};
    CGTable t{};
    for (int a = 0; a < 9; a++)
      for (int b = 0; b < 9; b++)
        for (int c = 0; c < 9; c++) {
            double g = 0.0;
            for (int i = 0; i < NTV[a]; i++)
              for (int j = 0; j < NTV[b]; j++)
                for (int k = 0; k < NTV[c]; k++)
                    g += TCV[a][i] * TCV[b][j] * TCV[c][k] *
                         sphint(TEV[a][i][0] + TEV[b][j][0] + TEV[c][k][0],
                                TEV[a][i][1] + TEV[b][j][1] + TEV[c][k][1],
                                TEV[a][i][2] + TEV[b][j][2] + TEV[c][k][2]);
            if (g < 1e-6 && g > -1e-6) g = 0.0;
            t.v[a][b][c] = (float)g;
        }
    return t;
}
constexpr CGTable CG_TAB = make_cg();

// ---------------- kernels -------------------------------------------------

__global__ void k_init(const int* __restrict__ z, const float* __restrict__ embed) {
    int idx = blockIdx.x * blockDim.x + threadIdx.x;      // float4 index
    if (idx >= NN * NODE_F4) return;
    if (idx < NN) g_cnt[idx] = 0;
    int r = idx % NODE_F4;
    int n = idx / NODE_F4;
    int f = r / 3, part = r % 3;
    float v0 = (part == 0) ? embed[z[n] * FF + f] : 0.0f;
    g_x4[idx] = make_float4(v0, 0.f, 0.f, 0.f);
}

__global__ void k_geom(const float* __restrict__ pos, const int* __restrict__ dst,
                       const int* __restrict__ src) {
    int e = blockIdx.x * blockDim.x + threadIdx.x;
    if (e >= EE) return;
    int s = src[e], d = dst[e];
    float dx = pos[s * 3 + 0] - pos[d * 3 + 0];
    float dy = pos[s * 3 + 1] - pos[d * 3 + 1];
    float dz = pos[s * 3 + 2] - pos[d * 3 + 2];
    float r = sqrtf(dx * dx + dy * dy + dz * dz + 1e-12f);
    float inv = 1.0f / r;
    float x = dx * inv, y = dy * inv, z = dz * inv;
    const float c0 = 0.28209479177387814f, c1 = 0.4886025119029199f,
                c2a = 1.0925484305920792f, c2b = 0.31539156525252005f,
                c2c = 0.5462742152960396f;
    float* g = &g_geo[(size_t)e * 25];
    g[0] = c0;
    g[1] = c1 * y;  g[2] = c1 * z;  g[3] = c1 * x;
    g[4] = c2a * x * y; g[5] = c2a * y * z;
    g[6] = c2b * (3.0f * z * z - 1.0f);
    g[7] = c2a * x * z; g[8] = c2c * (x * x - y * y);

    float u1 = 1.0f / (1.0f + r);
    float om = 1.0f - u1;
    float A[16], B[16];
    A[0] = 1.0f;
    #pragma unroll
    for (int k = 1; k < 16; k++) A[k] = A[k - 1] * u1;
    B[15] = 1.0f;
    #pragma unroll
    for (int k = 14; k >= 0; k--) B[k] = B[k + 1] * om;
    float t = r * 0.25f;
    float fc = 0.0f;
    if (t < 1.0f) {
        float den = 1.0f - t * t;
        fc = expf(-t * t / den);
    }
    const float binom[16] = {1.f,15.f,105.f,455.f,1365.f,3003.f,5005.f,6435.f,
                             6435.f,5005.f,3003.f,1365.f,455.f,105.f,15.f,1.f};
    #pragma unroll
    for (int k = 0; k < 16; k++) g[9 + k] = binom[k] * A[k] * B[k] * fc;
}

// -------- CSR build: histogram -> single-block scan -> scatter ------------
__global__ void k_hist(const int* __restrict__ dst) {
    int e = blockIdx.x * blockDim.x + threadIdx.x;
    if (e < EE) atomicAdd(&g_cnt[dst[e]], 1);
}

__global__ void __launch_bounds__(1024) k_scan() {
    __shared__ int ssum[1024];
    const int t = threadIdx.x;
    const int chunk = (NN + 1023) / 1024;           // 10
    const int beg = t * chunk;
    const int end = (beg + chunk < NN) ? beg + chunk : NN;
    int sum = 0;
    for (int i = beg; i < end; i++) sum += g_cnt[i];
    ssum[t] = sum;
    __syncthreads();
    for (int off = 1; off < 1024; off <<= 1) {
        int add = (t >= off) ? ssum[t - off] : 0;
        __syncthreads();
        ssum[t] += add;
        __syncthreads();
    }
    int run = (t > 0) ? ssum[t - 1] : 0;
    for (int i = beg; i < end; i++) {
        int c = g_cnt[i];
        g_off[i] = run;
        run += c;
        g_cnt[i] = 0;                               // reset: reused as cursor
    }
    if (t == 1023) g_off[NN] = EE;
}

__global__ void k_scat(const int* __restrict__ dst, const int* __restrict__ src) {
    int e = blockIdx.x * blockDim.x + threadIdx.x;
    if (e >= EE) return;
    int d = dst[e];
    int slot = g_off[d] + atomicAdd(&g_cnt[d], 1);
    g_csr_src[slot] = src[e];
    g_csr_eid[slot] = e;
}

// edge kernel: warp per dst node, register accumulation, NO atomics.
__global__ void __launch_bounds__(256, 2)
k_edge(const float* __restrict__ Wb_i) {
    const int lane = threadIdx.x & 31;
    const int warp = (blockIdx.x * blockDim.x + threadIdx.x) >> 5;
    const int nwarp = (gridDim.x * blockDim.x) >> 5;
    const int lsel = (lane < 25 ? lane : 0);

    float w0[16], w1[16], w2[16];
    #pragma unroll
    for (int n = 0; n < 16; n++) {
        w0[n] = Wb_i[(0 * 16 + n) * 32 + lane];
        w1[n] = Wb_i[(1 * 16 + n) * 32 + lane];
        w2[n] = Wb_i[(2 * 16 + n) * 32 + lane];
    }

    const float* gx = (const float*)g_x4;
    float* gy = (float*)g_y4;

    for (int n = warp; n < NN; n += nwarp) {
        const int beg = g_off[n], end = g_off[n + 1];

        float acc[9];
        #pragma unroll
        for (int c = 0; c < 9; c++) acc[c] = 0.f;

        int s = 0; float gv = 0.0f;
        if (beg < end) {
            s = g_csr_src[beg];
            gv = g_geo[(size_t)g_csr_eid[beg] * 25 + lsel];
        }
        for (int i = beg; i < end; i++) {
            // gather x[src] early
            const float4* xp4 = (const float4*)(gx + (size_t)s * (FF * NPAD) + lane * NPAD);
            float4 xv0 = xp4[0];
            float4 xv1 = xp4[1];
            float  xa8 = ((const float*)xp4)[8];

            // prefetch next edge of this node
            int s2 = 0; float gv2 = 0.0f;
            if (i + 1 < end) {
                s2 = g_csr_src[i + 1];
                gv2 = g_geo[(size_t)g_csr_eid[i + 1] * 25 + lsel];
            }

            float R0 = 0.f, R1 = 0.f, R2 = 0.f;
            #pragma unroll
            for (int k = 0; k < 16; k++) {
                float rn = __shfl_sync(0xffffffffu, gv, 9 + k);
                R0 = fmaf(rn, w0[k], R0);
                R1 = fmaf(rn, w1[k], R1);
                R2 = fmaf(rn, w2[k], R2);
            }
            float bfv[9];
            #pragma unroll
            for (int b = 0; b < 9; b++) {
                float sb = __shfl_sync(0xffffffffu, gv, b);
                bfv[b] = sb * (b == 0 ? R0 : (b < 4 ? R1 : R2));
            }
            float xa[9] = {xv0.x, xv0.y, xv0.z, xv0.w, xv1.x, xv1.y, xv1.z, xv1.w, xa8};

            float p[9];
            #pragma unroll
            for (int a = 0; a < 9; a++) p[a] = xa[a] * bfv[a];
#define ACCP(A,C) { constexpr float G_ = CG_TAB.v[A][A][C]; if (G_ != 0.0f) acc[C] = fmaf(p[A], G_, acc[C]); }
#define CROSS(A,B) float s##A##B = fmaf(xa[A], bfv[B], xa[B] * bfv[A]);
#define ACCS(A,B,C) { constexpr float G_ = CG_TAB.v[A][B][C]; if (G_ != 0.0f) acc[C] = fmaf(s##A##B, G_, acc[C]); }
            ACCP(0,0) ACCP(0,6) ACCP(0,8)
            ACCP(1,0) ACCP(1,6) ACCP(1,8)
            ACCP(2,0) ACCP(2,6) ACCP(2,8)
            ACCP(3,0) ACCP(3,6) ACCP(3,8)
            ACCP(4,0) ACCP(4,6) ACCP(4,8)
            ACCP(5,0) ACCP(5,6) ACCP(5,8)
            ACCP(6,0) ACCP(6,6) ACCP(6,8)
            ACCP(7,0) ACCP(7,6) ACCP(7,8)
            ACCP(8,0) ACCP(8,6) ACCP(8,8)

            CROSS(0,6) CROSS(0,8) CROSS(6,8)
            ACCS(0,6,0) ACCS(0,6,6) ACCS(0,6,8)
            ACCS(0,8,0) ACCS(0,8,6) ACCS(0,8,8)
            ACCS(6,8,0) ACCS(6,8,6) ACCS(6,8,8)

            CROSS(0,1) CROSS(6,1) CROSS(8,1) CROSS(3,4) CROSS(2,5)
            ACCS(0,1,1) ACCS(6,1,1) ACCS(8,1,1) ACCS(3,4,1) ACCS(2,5,1)

            CROSS(0,2) CROSS(6,2) CROSS(8,2) CROSS(3,7) CROSS(1,5)
            ACCS(0,2,2) ACCS(6,2,2) ACCS(8,2,2) ACCS(3,7,2) ACCS(1,5,2)

            CROSS(0,3) CROSS(6,3) CROSS(8,3) CROSS(1,4) CROSS(2,7)
            ACCS(0,3,3) ACCS(6,3,3) ACCS(8,3,3) ACCS(1,4,3) ACCS(2,7,3)

            CROSS(0,4) CROSS(6,4) CROSS(8,4) CROSS(1,3) CROSS(5,7)
            ACCS(0,4,4) ACCS(6,4,4) ACCS(8,4,4) ACCS(1,3,4) ACCS(5,7,4)

            CROSS(0,5) CROSS(6,5) CROSS(8,5) CROSS(1,2) CROSS(4,7)
            ACCS(0,5,5) ACCS(6,5,5) ACCS(8,5,5) ACCS(1,2,5) ACCS(4,7,5)

            CROSS(0,7) CROSS(6,7) CROSS(8,7) CROSS(2,3) CROSS(4,5)
            ACCS(0,7,7) ACCS(6,7,7) ACCS(8,7,7) ACCS(2,3,7) ACCS(4,5,7)
#undef ACCP
#undef CROSS
#undef ACCS
            s = s2; gv = gv2;
        }

        float4* yp4 = (float4*)(gy + (size_t)n * (FF * NPAD) + lane * NPAD);
        yp4[0] = make_float4(acc[0], acc[1], acc[2], acc[3]);
        yp4[1] = make_float4(acc[4], acc[5], acc[6], acc[7]);
        yp4[2] = make_float4(acc[8], 0.f, 0.f, 0.f);
    }
}

// node kernel: warp per node, lane = feature, shfl-broadcast matmul.
__global__ void __launch_bounds__(256)
k_node(const float* __restrict__ W1, const float* __restrict__ b1,
       const float* __restrict__ W2, const float* __restrict__ b2) {
    __shared__ float sW1[3 * 32 * 32], sW2[3 * 32 * 32], sb1[32], sb2[32];
    int t = threadIdx.x;
    for (int i = t; i < 3072; i += 256) { sW1[i] = W1[i]; sW2[i] = W2[i]; }
    if (t < 32) { sb1[t] = b1[t]; sb2[t] = b2[t]; }
    __syncthreads();

    int lane = t & 31;
    int n = (blockIdx.x * 256 + t) >> 5;
    if (n >= NN) return;

    const int base4 = n * NODE_F4 + lane * 3;
    float4 xA = g_x4[base4 + 0], xB = g_x4[base4 + 1], xC = g_x4[base4 + 2];
    float4 yA = g_y4[base4 + 0], yB = g_y4[base4 + 1], yC = g_y4[base4 + 2];

    const int DEGc[9] = {0, 1, 1, 1, 2, 2, 2, 2, 2};
    float yv[9], h[9], o[9];
    yv[0] = xA.x + yA.x; yv[1] = xA.y + yA.y; yv[2] = xA.z + yA.z; yv[3] = xA.w + yA.w;
    yv[4] = xB.x + yB.x; yv[5] = xB.y + yB.y; yv[6] = xB.z + yB.z; yv[7] = xB.w + yB.w;
    yv[8] = xC.x + yC.x;

    #pragma unroll
    for (int c = 0; c < 9; c++) {
        int d = DEGc[c];
        float acc = (c == 0) ? sb1[lane] : 0.0f;
        #pragma unroll
        for (int f = 0; f < 32; f++) {
            float v = __shfl_sync(0xffffffffu, yv[c], f);
            acc = fmaf(v, sW1[(d * 32 + f) * 32 + lane], acc);
        }
        h[c] = acc / (1.0f + __expf(-acc));   // silu
    }
    #pragma unroll
    for (int c = 0; c < 9; c++) {
        int d = DEGc[c];
        float acc = (c == 0) ? sb2[lane] : 0.0f;
        #pragma unroll
        for (int f = 0; f < 32; f++) {
            float v = __shfl_sync(0xffffffffu, h[c], f);
            acc = fmaf(v, sW2[(d * 32 + f) * 32 + lane], acc);
        }
        o[c] = acc;
    }
    g_x4[base4 + 0] = make_float4(xA.x + o[0], xA.y + o[1], xA.z + o[2], xA.w + o[3]);
    g_x4[base4 + 1] = make_float4(xB.x + o[4], xB.y + o[5], xB.z + o[6], xB.w + o[7]);
    g_x4[base4 + 2] = make_float4(xC.x + o[8], 0.f, 0.f, 0.f);
}

// output head: mono (N,4) then dip (N,3,4)
__global__ void __launch_bounds__(256)
k_out(const int* __restrict__ z, const float* __restrict__ pos,
      const float* __restrict__ Wt00, const float* __restrict__ Wt11,
      const float* __restrict__ Wmono, const float* __restrict__ ebias,
      float* __restrict__ out) {
    int lane = threadIdx.x & 31;
    int n = (blockIdx.x * blockDim.x + threadIdx.x) >> 5;
    if (n >= NN) return;
    const float* gx = (const float*)g_x4;
    const size_t nb = (size_t)n * (FF * NPAD) + lane * NPAD;

    float x0 = gx[nb + 0];
    float tj[4];
    #pragma unroll
    for (int j = 0; j < 4; j++) {
        float p = x0 * Wt00[lane * 4 + j];
        #pragma unroll
        for (int o = 16; o > 0; o >>= 1) p += __shfl_xor_sync(0xffffffffu, p, o);
        tj[j] = p;
    }
    if (lane < 4) {
        float m = 0.0f;
        #pragma unroll
        for (int k = 0; k < 4; k++) m = fmaf(tj[k], Wmono[k * 4 + lane], m);
        m += ebias[z[n]];
        out[n * 4 + lane] = m;
    }
    #pragma unroll
    for (int c = 0; c < 3; c++) {
        float xc = gx[nb + 1 + c];
        #pragma unroll
        for (int j = 0; j < 4; j++) {
            float p = xc * Wt11[lane * 4 + j];
            #pragma unroll
            for (int o = 16; o > 0; o >>= 1) p += __shfl_xor_sync(0xffffffffu, p, o);
            if (lane == 0) {
                float sv = p / (1.0f + expf(-p));
                sv = fminf(fmaxf(sv, -0.3f), 0.3f);
                out[NN * 4 + (n * 3 + c) * 4 + j] = sv + pos[n * 3 + c];
            }
        }
    }
}

// ---------------- launch --------------------------------------------------
extern "C" void kernel_launch(void* const* d_in, const int* in_sizes, int n_in,
                              void* d_out, int out_size) {
    const int*   z     = (const int*)d_in[0];
    const float* pos   = (const float*)d_in[1];
    const int*   dst   = (const int*)d_in[2];
    const int*   src   = (const int*)d_in[3];
    const float* embed = (const float*)d_in[4];
    const float* Wb    = (const float*)d_in[5];
    const float* W1    = (const float*)d_in[6];
    const float* b1    = (const float*)d_in[7];
    const float* W2    = (const float*)d_in[8];
    const float* b2    = (const float*)d_in[9];
    const float* Wt00  = (const float*)d_in[10];
    const float* Wt11  = (const float*)d_in[11];
    const float* Wmono = (const float*)d_in[12];
    const float* ebias = (const float*)d_in[13];
    float* out = (float*)d_out;

    k_init<<<(NN * NODE_F4 + 255) / 256, 256>>>(z, embed);      // launch 0
    k_geom<<<(EE + 255) / 256, 256>>>(pos, dst, src);           // launch 1
    k_hist<<<(EE + 255) / 256, 256>>>(dst);                     // launch 2
    k_scan<<<1, 1024>>>();                                      // launch 3
    k_scat<<<(EE + 255) / 256, 256>>>(dst, src);                // launch 4
    for (int i = 0; i < 3; i++) {
        k_edge<<<1250, 256>>>(Wb + i * 3 * 16 * 32);            // launch 5 = profiled
        k_node<<<(NN * 32 + 255) / 256, 256>>>(W1 + i * 3 * 32 * 32, b1 + i * 32,
                                               W2 + i * 3 * 32 * 32, b2 + i * 32);
    }
    k_out<<<(NN * 32 + 255) / 256, 256>>>(z, pos, Wt00, Wt11, Wmono, ebias, out);
}